// round 15
// baseline (speedup 1.0000x reference)
#include <cuda_runtime.h>
#include <cuda_bf16.h>
#include <cuda_fp16.h>
#include <cstdint>

#define S_LEN 4096
#define NHEAD 16
#define HD    64
#define WIN   128
#define QT    128
#define KT    64
#define NKT   6        // (QT + 2*WIN) / KT = 384/64

// ---- static smem byte offsets (rows x 128B, XOR-swizzled) ----
#define SM_Q   0              // 128 rows
#define SM_K   16384          // 64 rows
#define SM_V   24576          // 64 rows
#define SM_TOTAL 32768

// 0.125 * log2(e)
#define QSCALE 0.1803368801111204f
#define ONES_H2 0x3C003C00u

__device__ __forceinline__ uint32_t swz(uint32_t o) {
    return o ^ (((o >> 7) & 7u) << 4);
}
__device__ __forceinline__ uint32_t smem_u32(const void* p) {
    uint32_t a;
    asm("{ .reg .u64 t; cvta.to.shared.u64 t, %1; cvt.u32.u64 %0, t; }" : "=r"(a) : "l"(p));
    return a;
}
__device__ __forceinline__ void ldsm4(uint32_t addr, uint32_t* r) {
    asm volatile("ldmatrix.sync.aligned.m8n8.x4.shared.b16 {%0,%1,%2,%3}, [%4];"
        : "=r"(r[0]), "=r"(r[1]), "=r"(r[2]), "=r"(r[3]) : "r"(addr));
}
__device__ __forceinline__ void ldsm4t(uint32_t addr, uint32_t* r) {
    asm volatile("ldmatrix.sync.aligned.m8n8.x4.trans.shared.b16 {%0,%1,%2,%3}, [%4];"
        : "=r"(r[0]), "=r"(r[1]), "=r"(r[2]), "=r"(r[3]) : "r"(addr));
}
__device__ __forceinline__ void mma_f16(float* c, const uint32_t* a, uint32_t b0, uint32_t b1) {
    asm volatile("mma.sync.aligned.m16n8k16.row.col.f32.f16.f16.f32 "
        "{%0,%1,%2,%3}, {%4,%5,%6,%7}, {%8,%9}, {%0,%1,%2,%3};"
        : "+f"(c[0]), "+f"(c[1]), "+f"(c[2]), "+f"(c[3])
        : "r"(a[0]), "r"(a[1]), "r"(a[2]), "r"(a[3]), "r"(b0), "r"(b1));
}
__device__ __forceinline__ uint32_t pack_h2(float lo, float hi) {
    __half2 h = __floats2half2_rn(lo, hi);
    return *reinterpret_cast<uint32_t*>(&h);
}
__device__ __forceinline__ float ex2(float x) {
    float r;
    asm("ex2.approx.f32 %0, %1;" : "=f"(r) : "f"(x));
    return r;
}

__global__ void __launch_bounds__(128, 3)
wattn_mma_kernel(const float* __restrict__ Q, const float* __restrict__ K,
                 const float* __restrict__ V, float* __restrict__ O) {
    __shared__ char smem[SM_TOTAL];
    const uint32_t sb = smem_u32(smem);

    const int tid  = threadIdx.x;
    const int wid  = tid >> 5;
    const int lane = tid & 31;

    const int q0 = blockIdx.x * QT;
    const int b  = blockIdx.y >> 4;
    const int n  = blockIdx.y & 15;
    const size_t base = ((size_t)b * S_LEN * NHEAD + (size_t)n) * (size_t)HD;
    const int rs = NHEAD * HD;

    const int pc4 = tid & 15;        // dim-quad 0..15 (4 dims = 8 bytes)
    const int r0  = tid >> 4;        // row base 0..7

    // ---- load Q tile (128 rows) -> fp16, swizzled, scaled by 0.125*log2e ----
    #pragma unroll
    for (int i = 0; i < 16; i++) {
        const int r = r0 + i * 8;
        const float4 x = *(const float4*)(Q + base + (size_t)(q0 + r) * rs + pc4 * 4);
        const uint32_t off = swz((uint32_t)(r * 128 + pc4 * 8));
        *(uint2*)(smem + SM_Q + off) =
            make_uint2(pack_h2(x.x * QSCALE, x.y * QSCALE),
                       pack_h2(x.z * QSCALE, x.w * QSCALE));
    }
    __syncthreads();

    // ---- persistent Q a-frags: 4 k-steps x 2 q-frags ----
    uint32_t qh[4][2][4];
    {
        const int qa_dsel = ((lane >> 4) & 1) * 16;
        #pragma unroll
        for (int ks = 0; ks < 4; ks++)
            #pragma unroll
            for (int qf = 0; qf < 2; qf++) {
                const int row = wid * 32 + qf * 16 + (lane & 15);
                ldsm4(sb + SM_Q + swz((uint32_t)(row * 128 + ks * 32 + qa_dsel)), qh[ks][qf]);
            }
    }

    const int g = lane >> 2;
    const int t = lane & 3;
    // 4 output rows per thread: [qf=0: g, g+8][qf=1: 16+g, 24+g]
    int   gq[4];
    int   wlo[4];
    uint32_t rng[4];
    #pragma unroll
    for (int j = 0; j < 4; j++) {
        gq[j] = q0 + wid * 32 + (j >> 1) * 16 + (j & 1) * 8 + g;
        const int lo = (gq[j] - WIN) > 0 ? (gq[j] - WIN) : 0;
        const int hi = (gq[j] + WIN) < (S_LEN - 1) ? (gq[j] + WIN) : (S_LEN - 1);
        wlo[j] = lo;
        rng[j] = (uint32_t)(hi - lo);
    }

    float oc0[8][4], oc1[8][4];
    #pragma unroll
    for (int i = 0; i < 8; i++)
        #pragma unroll
        for (int j = 0; j < 4; j++) { oc0[i][j] = 0.0f; oc1[i][j] = 0.0f; }
    float ls0[4] = {0.f, 0.f, 0.f, 0.f};
    float ls1[4] = {0.f, 0.f, 0.f, 0.f};

    const int kb_key  = (lane & 7) + ((lane & 16) ? 8 : 0);
    const int kb_dsel = (lane & 8) ? 16 : 0;
    const int vb_key  = (lane & 7) + ((lane & 8) ? 8 : 0);
    const int vb_dsel = (lane & 16) ? 16 : 0;
    const int glo = 2 * wid;         // warp group range [glo, glo+17]

    for (int kt = 0; kt < NKT; kt++) {
        const int kbase = q0 - WIN + kt * KT;
        const int kt4 = kt * 4;

        __syncthreads();

        // ---- load K, V (fp16) tiles, swizzled [key][dim] ----
        #pragma unroll
        for (int i = 0; i < 8; i++) {
            const int r = r0 + i * 8;
            const int gk = kbase + r;
            float4 xk = make_float4(0.f, 0.f, 0.f, 0.f);
            float4 xv = make_float4(0.f, 0.f, 0.f, 0.f);
            if (gk >= 0 && gk < S_LEN) {
                xk = *(const float4*)(K + base + (size_t)gk * rs + pc4 * 4);
                xv = *(const float4*)(V + base + (size_t)gk * rs + pc4 * 4);
            }
            const uint32_t off = swz((uint32_t)(r * 128 + pc4 * 8));
            *(uint2*)(smem + SM_K + off) =
                make_uint2(pack_h2(xk.x, xk.y), pack_h2(xk.z, xk.w));
            *(uint2*)(smem + SM_V + off) =
                make_uint2(pack_h2(xv.x, xv.y), pack_h2(xv.z, xv.w));
        }
        __syncthreads();

        int klo[4];
        #pragma unroll
        for (int j = 0; j < 4; j++) klo[j] = wlo[j] - kbase;

        #pragma unroll
        for (int s = 0; s < 4; s++) {
            const int g16 = kt4 + s;
            if (g16 < glo || g16 > glo + 17) continue;       // warp-uniform skip

            // ---- QK: 4 independent depth-4 chains, K frags shared across qf ----
            float sc[4][4];
            #pragma unroll
            for (int i = 0; i < 4; i++)
                #pragma unroll
                for (int j = 0; j < 4; j++) sc[i][j] = 0.0f;

            #pragma unroll
            for (int ks = 0; ks < 4; ks++) {
                uint32_t bh[4];
                ldsm4(sb + SM_K + swz((uint32_t)((s * 16 + kb_key) * 128 + ks * 32 + kb_dsel)), bh);
                mma_f16(sc[0], qh[ks][0], bh[0], bh[1]);
                mma_f16(sc[1], qh[ks][0], bh[2], bh[3]);
                mma_f16(sc[2], qh[ks][1], bh[0], bh[1]);
                mma_f16(sc[3], qh[ks][1], bh[2], bh[3]);
            }

            // ---- mask + exp2 (interior groups: provably unmasked for all 32 rows) ----
            const int kb16 = kbase + s * 16;
            const bool noMask = (g16 >= glo + 2) && (g16 <= glo + 15) &&
                                (kb16 >= 0) && (kb16 + 16 <= S_LEN);
            float p0[8], p1[8];
            if (noMask) {
                #pragma unroll
                for (int j = 0; j < 4; j++) {
                    p0[j]     = ex2(sc[0][j]);
                    p0[4 + j] = ex2(sc[1][j]);
                    p1[j]     = ex2(sc[2][j]);
                    p1[4 + j] = ex2(sc[3][j]);
                }
            } else {
                const int ia = s * 16 + 2 * t;
                const int ib = ia + 8;
                p0[0] = ((uint32_t)(ia - klo[0])     <= rng[0]) ? ex2(sc[0][0]) : 0.0f;
                p0[1] = ((uint32_t)(ia + 1 - klo[0]) <= rng[0]) ? ex2(sc[0][1]) : 0.0f;
                p0[2] = ((uint32_t)(ia - klo[1])     <= rng[1]) ? ex2(sc[0][2]) : 0.0f;
                p0[3] = ((uint32_t)(ia + 1 - klo[1]) <= rng[1]) ? ex2(sc[0][3]) : 0.0f;
                p0[4] = ((uint32_t)(ib - klo[0])     <= rng[0]) ? ex2(sc[1][0]) : 0.0f;
                p0[5] = ((uint32_t)(ib + 1 - klo[0]) <= rng[0]) ? ex2(sc[1][1]) : 0.0f;
                p0[6] = ((uint32_t)(ib - klo[1])     <= rng[1]) ? ex2(sc[1][2]) : 0.0f;
                p0[7] = ((uint32_t)(ib + 1 - klo[1]) <= rng[1]) ? ex2(sc[1][3]) : 0.0f;
                p1[0] = ((uint32_t)(ia - klo[2])     <= rng[2]) ? ex2(sc[2][0]) : 0.0f;
                p1[1] = ((uint32_t)(ia + 1 - klo[2]) <= rng[2]) ? ex2(sc[2][1]) : 0.0f;
                p1[2] = ((uint32_t)(ia - klo[3])     <= rng[3]) ? ex2(sc[2][2]) : 0.0f;
                p1[3] = ((uint32_t)(ia + 1 - klo[3]) <= rng[3]) ? ex2(sc[2][3]) : 0.0f;
                p1[4] = ((uint32_t)(ib - klo[2])     <= rng[2]) ? ex2(sc[3][0]) : 0.0f;
                p1[5] = ((uint32_t)(ib + 1 - klo[2]) <= rng[2]) ? ex2(sc[3][1]) : 0.0f;
                p1[6] = ((uint32_t)(ib - klo[3])     <= rng[3]) ? ex2(sc[3][2]) : 0.0f;
                p1[7] = ((uint32_t)(ib + 1 - klo[3]) <= rng[3]) ? ex2(sc[3][3]) : 0.0f;
            }

            uint32_t phi0[4], phi1[4];
            phi0[0] = pack_h2(p0[0], p0[1]);
            phi0[1] = pack_h2(p0[2], p0[3]);
            phi0[2] = pack_h2(p0[4], p0[5]);
            phi0[3] = pack_h2(p0[6], p0[7]);
            phi1[0] = pack_h2(p1[0], p1[1]);
            phi1[1] = pack_h2(p1[2], p1[3]);
            phi1[2] = pack_h2(p1[4], p1[5]);
            phi1[3] = pack_h2(p1[6], p1[7]);

            mma_f16(ls0, phi0, ONES_H2, ONES_H2);
            mma_f16(ls1, phi1, ONES_H2, ONES_H2);

            // ---- PV: V frags shared across both q-frags ----
            #pragma unroll
            for (int dg = 0; dg < 4; dg++) {
                uint32_t vh[4];
                ldsm4t(sb + SM_V + swz((uint32_t)((s * 16 + vb_key) * 128 + dg * 32 + vb_dsel)), vh);
                mma_f16(oc0[2 * dg],     phi0, vh[0], vh[1]);
                mma_f16(oc0[2 * dg + 1], phi0, vh[2], vh[3]);
                mma_f16(oc1[2 * dg],     phi1, vh[0], vh[1]);
                mma_f16(oc1[2 * dg + 1], phi1, vh[2], vh[3]);
            }
        }
    }

    const float inv00 = 1.0f / ls0[0];
    const float inv01 = 1.0f / ls0[2];
    const float inv10 = 1.0f / ls1[0];
    const float inv11 = 1.0f / ls1[2];

    // ---- write output: 4 rows per thread ----
    float* d0 = O + base + (size_t)gq[0] * rs;
    float* d1 = O + base + (size_t)gq[1] * rs;
    float* d2 = O + base + (size_t)gq[2] * rs;
    float* d3 = O + base + (size_t)gq[3] * rs;
    #pragma unroll
    for (int nt = 0; nt < 8; nt++) {
        const int d = nt * 8 + 2 * t;
        *(float2*)(d0 + d) = make_float2(oc0[nt][0] * inv00, oc0[nt][1] * inv00);
        *(float2*)(d1 + d) = make_float2(oc0[nt][2] * inv01, oc0[nt][3] * inv01);
        *(float2*)(d2 + d) = make_float2(oc1[nt][0] * inv10, oc1[nt][1] * inv10);
        *(float2*)(d3 + d) = make_float2(oc1[nt][2] * inv11, oc1[nt][3] * inv11);
    }
}

extern "C" void kernel_launch(void* const* d_in, const int* in_sizes, int n_in,
                              void* d_out, int out_size) {
    const float* q = (const float*)d_in[0];
    const float* k = (const float*)d_in[1];
    const float* v = (const float*)d_in[2];
    float* out = (float*)d_out;

    const int b = in_sizes[0] / (S_LEN * NHEAD * HD);

    dim3 grid(S_LEN / QT, b * NHEAD);
    wattn_mma_kernel<<<grid, 128>>>(q, k, v, out);
}

// round 16
// speedup vs baseline: 1.4541x; 1.4541x over previous
#include <cuda_runtime.h>
#include <cuda_bf16.h>
#include <cuda_fp16.h>
#include <cstdint>

#define S_LEN 4096
#define NHEAD 16
#define HD    64
#define WIN   128
#define QT    64
#define KT    128
#define NKT   3        // (QT + 2*WIN) / KT = 384/128

// ---- static smem byte offsets (Q: 64 rows, K/V: 128 rows x 128B, swizzled) ----
#define SM_Q   0
#define SM_K   8192
#define SM_V   24576
#define SM_TOTAL 40960

// 0.125 * log2(e)
#define QSCALE 0.1803368801111204f
#define ONES_H2 0x3C003C00u

__device__ __forceinline__ uint32_t swz(uint32_t o) {
    return o ^ (((o >> 7) & 7u) << 4);
}
__device__ __forceinline__ uint32_t smem_u32(const void* p) {
    uint32_t a;
    asm("{ .reg .u64 t; cvta.to.shared.u64 t, %1; cvt.u32.u64 %0, t; }" : "=r"(a) : "l"(p));
    return a;
}
__device__ __forceinline__ void ldsm4(uint32_t addr, uint32_t* r) {
    asm volatile("ldmatrix.sync.aligned.m8n8.x4.shared.b16 {%0,%1,%2,%3}, [%4];"
        : "=r"(r[0]), "=r"(r[1]), "=r"(r[2]), "=r"(r[3]) : "r"(addr));
}
__device__ __forceinline__ void ldsm4t(uint32_t addr, uint32_t* r) {
    asm volatile("ldmatrix.sync.aligned.m8n8.x4.trans.shared.b16 {%0,%1,%2,%3}, [%4];"
        : "=r"(r[0]), "=r"(r[1]), "=r"(r[2]), "=r"(r[3]) : "r"(addr));
}
__device__ __forceinline__ void mma_f16(float* c, const uint32_t* a, uint32_t b0, uint32_t b1) {
    asm volatile("mma.sync.aligned.m16n8k16.row.col.f32.f16.f16.f32 "
        "{%0,%1,%2,%3}, {%4,%5,%6,%7}, {%8,%9}, {%0,%1,%2,%3};"
        : "+f"(c[0]), "+f"(c[1]), "+f"(c[2]), "+f"(c[3])
        : "r"(a[0]), "r"(a[1]), "r"(a[2]), "r"(a[3]), "r"(b0), "r"(b1));
}
__device__ __forceinline__ uint32_t pack_h2(float lo, float hi) {
    __half2 h = __floats2half2_rn(lo, hi);
    return *reinterpret_cast<uint32_t*>(&h);
}
__device__ __forceinline__ float ex2(float x) {
    float r;
    asm("ex2.approx.f32 %0, %1;" : "=f"(r) : "f"(x));
    return r;
}

__global__ void __launch_bounds__(128, 3)
wattn_mma_kernel(const float* __restrict__ Q, const float* __restrict__ K,
                 const float* __restrict__ V, float* __restrict__ O) {
    __shared__ char smem[SM_TOTAL];
    const uint32_t sb = smem_u32(smem);

    const int tid  = threadIdx.x;
    const int wid  = tid >> 5;
    const int lane = tid & 31;

    const int q0 = blockIdx.x * QT;
    const int b  = blockIdx.y >> 4;
    const int n  = blockIdx.y & 15;
    const size_t base = ((size_t)b * S_LEN * NHEAD + (size_t)n) * (size_t)HD;
    const int rs = NHEAD * HD;

    const int pc4 = tid & 15;        // dim-quad 0..15 (4 dims = 8 bytes)
    const int r0  = tid >> 4;        // row base 0..7

    // ---- load Q tile -> fp16, swizzled [row][dim], scaled by 0.125*log2e ----
    {
        #pragma unroll
        for (int i = 0; i < 8; i++) {
            const int r = r0 + i * 8;
            const float4 x = *(const float4*)(Q + base + (size_t)(q0 + r) * rs + pc4 * 4);
            const uint32_t off = swz((uint32_t)(r * 128 + pc4 * 8));
            *(uint2*)(smem + SM_Q + off) =
                make_uint2(pack_h2(x.x * QSCALE, x.y * QSCALE),
                           pack_h2(x.z * QSCALE, x.w * QSCALE));
        }
    }

    const int g = lane >> 2;
    const int t = lane & 3;
    const int gq0 = q0 + wid * 16 + g;
    const int gq1 = gq0 + 8;
    const int wlo0 = (gq0 - WIN) > 0 ? (gq0 - WIN) : 0;
    const int whi0 = (gq0 + WIN) < (S_LEN - 1) ? (gq0 + WIN) : (S_LEN - 1);
    const int wlo1 = (gq1 - WIN) > 0 ? (gq1 - WIN) : 0;
    const int whi1 = (gq1 + WIN) < (S_LEN - 1) ? (gq1 + WIN) : (S_LEN - 1);
    const uint32_t rng0 = (uint32_t)(whi0 - wlo0);
    const uint32_t rng1 = (uint32_t)(whi1 - wlo1);

    float oc[8][4];
    #pragma unroll
    for (int i = 0; i < 8; i++)
        #pragma unroll
        for (int j = 0; j < 4; j++) oc[i][j] = 0.0f;
    float lsc[4] = {0.0f, 0.0f, 0.0f, 0.0f};   // row-sum c-frag

    // ldmatrix addressing (lane-dependent, loop-invariant)
    const int qa_row  = wid * 16 + (lane & 15);
    const int qa_dsel = ((lane >> 4) & 1) * 16;
    const int kb_key  = (lane & 7) + ((lane & 16) ? 8 : 0);
    const int kb_dsel = (lane & 8) ? 16 : 0;
    const int vb_key  = (lane & 7) + ((lane & 8) ? 8 : 0);
    const int vb_dsel = (lane & 16) ? 16 : 0;

    for (int kt = 0; kt < NKT; kt++) {
        const int kbase = q0 - WIN + kt * KT;

        __syncthreads();

        // ---- load K (fp16) and V (fp16) tiles: 128 rows, swizzled [key][dim] ----
        #pragma unroll
        for (int i = 0; i < 16; i++) {
            const int r = r0 + i * 8;
            const int gk = kbase + r;
            float4 xk = make_float4(0.f, 0.f, 0.f, 0.f);
            float4 xv = make_float4(0.f, 0.f, 0.f, 0.f);
            if (gk >= 0 && gk < S_LEN) {
                xk = *(const float4*)(K + base + (size_t)gk * rs + pc4 * 4);
                xv = *(const float4*)(V + base + (size_t)gk * rs + pc4 * 4);
            }
            const uint32_t off = swz((uint32_t)(r * 128 + pc4 * 8));
            *(uint2*)(smem + SM_K + off) =
                make_uint2(pack_h2(xk.x, xk.y), pack_h2(xk.z, xk.w));
            *(uint2*)(smem + SM_V + off) =
                make_uint2(pack_h2(xv.x, xv.y), pack_h2(xv.z, xv.w));
        }
        __syncthreads();

        const int klo0 = wlo0 - kbase;
        const int klo1 = wlo1 - kbase;

        // ---- two 64-key halves, each identical to the proven KT=64 block ----
        #pragma unroll
        for (int half = 0; half < 2; half++) {
            const int sg0 = half * 4;            // group index base within tile
            const int kt4 = kt * 8 + sg0;        // absolute 16-key group base

            // ---- QK^T: S[16q x 64k], single-term fp16, group skip ----
            float sc[8][4];
            #pragma unroll
            for (int i = 0; i < 8; i++)
                #pragma unroll
                for (int j = 0; j < 4; j++) sc[i][j] = 0.0f;

            #pragma unroll
            for (int ks = 0; ks < 4; ks++) {
                uint32_t qh[4];
                const uint32_t qoff = swz((uint32_t)(qa_row * 128 + ks * 32 + qa_dsel));
                ldsm4(sb + SM_Q + qoff, qh);
                #pragma unroll
                for (int ng = 0; ng < 4; ng++) {
                    const int g16 = kt4 + ng;
                    if (g16 < wid || g16 > wid + 16) continue;   // warp-uniform skip
                    const uint32_t off = swz((uint32_t)(((sg0 + ng) * 16 + kb_key) * 128 + ks * 32 + kb_dsel));
                    uint32_t bh[4];
                    ldsm4(sb + SM_K + off, bh);
                    mma_f16(sc[2 * ng],     qh, bh[0], bh[1]);
                    mma_f16(sc[2 * ng + 1], qh, bh[2], bh[3]);
                }
            }

            // ---- per 16-key group: mask + exp2 + pack P(fp16) + lsum-MMA + PV ----
            #pragma unroll
            for (int s = 0; s < 4; s++) {
                const int g16 = kt4 + s;
                if (g16 < wid || g16 > wid + 16) continue;       // warp-uniform skip
                const int sg = sg0 + s;

                // interior groups: every row's window provably covers all 16 keys
                const int kb16 = kbase + sg * 16;
                const bool noMask = (g16 > wid) && (g16 < wid + 16) &&
                                    (kb16 >= 0) && (kb16 + 16 <= S_LEN);
                float p[8];
                if (noMask) {
                    p[0] = ex2(sc[2*s][0]);   p[1] = ex2(sc[2*s][1]);
                    p[2] = ex2(sc[2*s][2]);   p[3] = ex2(sc[2*s][3]);
                    p[4] = ex2(sc[2*s+1][0]); p[5] = ex2(sc[2*s+1][1]);
                    p[6] = ex2(sc[2*s+1][2]); p[7] = ex2(sc[2*s+1][3]);
                } else {
                    const int ia = sg * 16 + 2 * t;
                    const int ib = ia + 8;
                    p[0] = ((uint32_t)(ia - klo0)     <= rng0) ? ex2(sc[2*s][0])   : 0.0f;
                    p[1] = ((uint32_t)(ia + 1 - klo0) <= rng0) ? ex2(sc[2*s][1])   : 0.0f;
                    p[2] = ((uint32_t)(ia - klo1)     <= rng1) ? ex2(sc[2*s][2])   : 0.0f;
                    p[3] = ((uint32_t)(ia + 1 - klo1) <= rng1) ? ex2(sc[2*s][3])   : 0.0f;
                    p[4] = ((uint32_t)(ib - klo0)     <= rng0) ? ex2(sc[2*s+1][0]) : 0.0f;
                    p[5] = ((uint32_t)(ib + 1 - klo0) <= rng0) ? ex2(sc[2*s+1][1]) : 0.0f;
                    p[6] = ((uint32_t)(ib - klo1)     <= rng1) ? ex2(sc[2*s+1][2]) : 0.0f;
                    p[7] = ((uint32_t)(ib + 1 - klo1) <= rng1) ? ex2(sc[2*s+1][3]) : 0.0f;
                }

                uint32_t phi[4];
                phi[0] = pack_h2(p[0], p[1]);
                phi[1] = pack_h2(p[2], p[3]);
                phi[2] = pack_h2(p[4], p[5]);
                phi[3] = pack_h2(p[6], p[7]);

                mma_f16(lsc, phi, ONES_H2, ONES_H2);   // row sums via ones-B

                #pragma unroll
                for (int dg = 0; dg < 4; dg++) {
                    const uint32_t off = swz((uint32_t)((sg * 16 + vb_key) * 128 + dg * 32 + vb_dsel));
                    uint32_t vh[4];
                    ldsm4t(sb + SM_V + off, vh);
                    mma_f16(oc[2 * dg],     phi, vh[0], vh[1]);
                    mma_f16(oc[2 * dg + 1], phi, vh[2], vh[3]);
                }
            }
        }
    }

    const float inv0 = 1.0f / lsc[0];
    const float inv1 = 1.0f / lsc[2];

    // ---- write output: O[b][gq][n][d] ----
    float* dst0 = O + base + (size_t)gq0 * rs;
    float* dst1 = O + base + (size_t)gq1 * rs;
    #pragma unroll
    for (int nt = 0; nt < 8; nt++) {
        const int d = nt * 8 + 2 * t;
        *(float2*)(dst0 + d) = make_float2(oc[nt][0] * inv0, oc[nt][1] * inv0);
        *(float2*)(dst1 + d) = make_float2(oc[nt][2] * inv1, oc[nt][3] * inv1);
    }
}

extern "C" void kernel_launch(void* const* d_in, const int* in_sizes, int n_in,
                              void* d_out, int out_size) {
    const float* q = (const float*)d_in[0];
    const float* k = (const float*)d_in[1];
    const float* v = (const float*)d_in[2];
    float* out = (float*)d_out;

    const int b = in_sizes[0] / (S_LEN * NHEAD * HD);

    dim3 grid(S_LEN / QT, b * NHEAD);
    wattn_mma_kernel<<<grid, 128>>>(q, k, v, out);
}